// round 7
// baseline (speedup 1.0000x reference)
#include <cuda_runtime.h>
#include <cuda_bf16.h>
#include <cstdint>

#define BATCH 64
#define SEQ   512
#define DIM   1024
#define TAGS  32
#define NCRF  32   // CRF blocks (2 batches each), scheduled first

__device__ float g_x[BATCH * SEQ * TAGS];
__device__ float g_logz[BATCH];
__device__ float g_score[BATCH];
__device__ int   g_flag[BATCH * 8];   // per (batch, 64-step chunk) release flag
__device__ int   g_done;              // ticket counter for final reduce

// ---------------------------------------------------------------------------
__device__ __forceinline__ void mma_bf16(float& d0, float& d1, float& d2, float& d3,
                                         uint32_t a0, uint32_t a1, uint32_t a2, uint32_t a3,
                                         uint32_t b0, uint32_t b1) {
    asm volatile(
        "mma.sync.aligned.m16n8k16.row.col.f32.bf16.bf16.f32 "
        "{%0,%1,%2,%3}, {%4,%5,%6,%7}, {%8,%9}, {%0,%1,%2,%3};\n"
        : "+f"(d0), "+f"(d1), "+f"(d2), "+f"(d3)
        : "r"(a0), "r"(a1), "r"(a2), "r"(a3), "r"(b0), "r"(b1));
}

__device__ __forceinline__ uint32_t pack_bf16(float lo, float hi) {
    __nv_bfloat162 h = __floats2bfloat162_rn(lo, hi);
    return *reinterpret_cast<uint32_t*>(&h);
}

__device__ __forceinline__ void wait_flag(const int* f) {
    int v;
    do {
        asm volatile("ld.global.acquire.gpu.b32 %0, [%1];"
                     : "=r"(v) : "l"(f) : "memory");
        if (!v) __nanosleep(64);
    } while (!v);
}

__device__ __forceinline__ int tag_at(const int* __restrict__ tg, int idx, bool is64) {
    return is64 ? __ldg(tg + 2 * idx) : __ldg(tg + idx);
}

// 32-FMA dot of replicated alpha (smem) with per-lane column Tc.
__device__ __forceinline__ float dot32(const float* __restrict__ q,
                                       const float* __restrict__ Tc) {
    const float4 q0 = *reinterpret_cast<const float4*>(q + 0);
    const float4 q1 = *reinterpret_cast<const float4*>(q + 4);
    const float4 q2 = *reinterpret_cast<const float4*>(q + 8);
    const float4 q3 = *reinterpret_cast<const float4*>(q + 12);
    const float4 q4 = *reinterpret_cast<const float4*>(q + 16);
    const float4 q5 = *reinterpret_cast<const float4*>(q + 20);
    const float4 q6 = *reinterpret_cast<const float4*>(q + 24);
    const float4 q7 = *reinterpret_cast<const float4*>(q + 28);
    float s0 = q0.x * Tc[0],  s1 = q0.y * Tc[1];
    float s2 = q0.z * Tc[2],  s3 = q0.w * Tc[3];
    s0 = fmaf(q1.x, Tc[4],  s0); s1 = fmaf(q1.y, Tc[5],  s1);
    s2 = fmaf(q1.z, Tc[6],  s2); s3 = fmaf(q1.w, Tc[7],  s3);
    s0 = fmaf(q2.x, Tc[8],  s0); s1 = fmaf(q2.y, Tc[9],  s1);
    s2 = fmaf(q2.z, Tc[10], s2); s3 = fmaf(q2.w, Tc[11], s3);
    s0 = fmaf(q3.x, Tc[12], s0); s1 = fmaf(q3.y, Tc[13], s1);
    s2 = fmaf(q3.z, Tc[14], s2); s3 = fmaf(q3.w, Tc[15], s3);
    s0 = fmaf(q4.x, Tc[16], s0); s1 = fmaf(q4.y, Tc[17], s1);
    s2 = fmaf(q4.z, Tc[18], s2); s3 = fmaf(q4.w, Tc[19], s3);
    s0 = fmaf(q5.x, Tc[20], s0); s1 = fmaf(q5.y, Tc[21], s1);
    s2 = fmaf(q5.z, Tc[22], s2); s3 = fmaf(q5.w, Tc[23], s3);
    s0 = fmaf(q6.x, Tc[24], s0); s1 = fmaf(q6.y, Tc[25], s1);
    s2 = fmaf(q6.z, Tc[26], s2); s3 = fmaf(q6.w, Tc[27], s3);
    s0 = fmaf(q7.x, Tc[28], s0); s1 = fmaf(q7.y, Tc[29], s1);
    s2 = fmaf(q7.z, Tc[30], s2); s3 = fmaf(q7.w, Tc[31], s3);
    return (s0 + s1) + (s2 + s3);
}

#define ASTRIDE 68
#define WSTRIDE 40

// ---------------------------------------------------------------------------
// Fused kernel. blocks [0,NCRF): CRF (batches 2i, 2i+1); [NCRF, NCRF+512): GEMM.
// ---------------------------------------------------------------------------
__global__ __launch_bounds__(256, 2)
void fused_kernel(const float* __restrict__ feat,
                  const int*   __restrict__ tags,
                  const float* __restrict__ Wg,
                  const float* __restrict__ bias,
                  const float* __restrict__ start_t,
                  const float* __restrict__ end_t,
                  const float* __restrict__ trans,
                  float* __restrict__ out) {
    if (blockIdx.x >= NCRF) {
        // ==================== GEMM producer (known good) ====================
        __shared__ uint32_t Asm[64 * ASTRIDE];
        __shared__ uint32_t Wp [64 * WSTRIDE];

        const int tid  = threadIdx.x;
        const int lane = tid & 31;
        const int w    = tid >> 5;
        const int m0   = (blockIdx.x - NCRF) * 64;

        float4 areg[8];
        float  wlo[8], whi[8];

#pragma unroll
        for (int i = 0; i < 8; i++) {
            const int idx = tid + i * 256;
            const int row = idx >> 5, kq = idx & 31;
            areg[i] = *reinterpret_cast<const float4*>(
                feat + (size_t)(m0 + row) * DIM + 4 * kq);
        }
#pragma unroll
        for (int i = 0; i < 8; i++) {
            const int idx = tid + i * 256;
            const int kp = idx >> 5, n = idx & 31;
            wlo[i] = Wg[(size_t)(2 * kp) * TAGS + n];
            whi[i] = Wg[(size_t)(2 * kp + 1) * TAGS + n];
        }

        float acc[2][4];
#pragma unroll
        for (int f = 0; f < 2; f++)
#pragma unroll
            for (int j = 0; j < 4; j++) acc[f][j] = 0.f;

        const int rb = (w & 3) * 16;
        const int nb = (w >> 2) * 16;
        const int g  = lane >> 2;
        const int t  = lane & 3;

        for (int c = 0; c < 8; c++) {
#pragma unroll
            for (int i = 0; i < 8; i++) {
                const int idx = tid + i * 256;
                const int row = idx >> 5, kq = idx & 31;
                Asm[row * ASTRIDE + 2 * kq]     = pack_bf16(areg[i].x, areg[i].y);
                Asm[row * ASTRIDE + 2 * kq + 1] = pack_bf16(areg[i].z, areg[i].w);
            }
#pragma unroll
            for (int i = 0; i < 8; i++) {
                const int idx = tid + i * 256;
                const int kp = idx >> 5, n = idx & 31;
                Wp[kp * WSTRIDE + n] = pack_bf16(wlo[i], whi[i]);
            }
            __syncthreads();

            if (c < 7) {
                const int kc = (c + 1) * 128;
#pragma unroll
                for (int i = 0; i < 8; i++) {
                    const int idx = tid + i * 256;
                    const int row = idx >> 5, kq = idx & 31;
                    areg[i] = *reinterpret_cast<const float4*>(
                        feat + (size_t)(m0 + row) * DIM + kc + 4 * kq);
                }
#pragma unroll
                for (int i = 0; i < 8; i++) {
                    const int idx = tid + i * 256;
                    const int kp = idx >> 5, n = idx & 31;
                    wlo[i] = Wg[(size_t)(kc + 2 * kp) * TAGS + n];
                    whi[i] = Wg[(size_t)(kc + 2 * kp + 1) * TAGS + n];
                }
            }

#pragma unroll
            for (int kf = 0; kf < 8; kf++) {
                const int kw = 8 * kf;
                const uint32_t a0 = Asm[(rb + g)     * ASTRIDE + kw + t];
                const uint32_t a1 = Asm[(rb + g + 8) * ASTRIDE + kw + t];
                const uint32_t a2 = Asm[(rb + g)     * ASTRIDE + kw + 4 + t];
                const uint32_t a3 = Asm[(rb + g + 8) * ASTRIDE + kw + 4 + t];
#pragma unroll
                for (int f = 0; f < 2; f++) {
                    const uint32_t b0 = Wp[(kw + t)     * WSTRIDE + nb + 8 * f + g];
                    const uint32_t b1 = Wp[(kw + 4 + t) * WSTRIDE + nb + 8 * f + g];
                    mma_bf16(acc[f][0], acc[f][1], acc[f][2], acc[f][3],
                             a0, a1, a2, a3, b0, b1);
                }
            }
            __syncthreads();
        }

        const int c2 = 2 * t;
        const int row0 = m0 + rb + g;
#pragma unroll
        for (int f = 0; f < 2; f++) {
            const int col = nb + 8 * f + c2;
            const float bv0 = bias[col], bv1 = bias[col + 1];
            *reinterpret_cast<float2*>(g_x + (size_t)row0 * TAGS + col) =
                make_float2(acc[f][0] + bv0, acc[f][1] + bv1);
            *reinterpret_cast<float2*>(g_x + (size_t)(row0 + 8) * TAGS + col) =
                make_float2(acc[f][2] + bv0, acc[f][3] + bv1);
        }

        __threadfence();
        __syncthreads();
        if (tid == 0) {
            const int fb = m0 >> 9;
            const int fc = (m0 >> 6) & 7;
            atomicExch(&g_flag[fb * 8 + fc], 1);
        }
        return;
    }

    // ==================== CRF consumer: 2 batches per block ====================
    const unsigned F = 0xffffffffu;
    const int tid  = threadIdx.x;
    const int lane = tid & 31;
    const int warp = tid >> 5;
    const int bA = blockIdx.x * 2;
    const int bB = bA + 1;

    __shared__ __align__(16) float psA[2][32];
    __shared__ __align__(16) float psB[2][32];
    __shared__ int s_last;

    if (warp < 3) {
        // tag dtype detection (same result in every warp)
        const int v1 = tags[2 * lane + 1];
        const int v2 = tags[2 * lane + 65];
        const bool okd = (v1 == 0 || v1 == -1) && (v2 == 0 || v2 == -1);
        const bool is64 = __all_sync(F, okd);

        if (warp > 0) {
            // ---------- numerator score for batch bA (warp1) / bB (warp2) ----------
            const int b = (warp == 1) ? bA : bB;
            const int base = b * SEQ;
            const float* xrow = g_x + (size_t)b * SEQ * TAGS;
            int* flags = &g_flag[b * 8];

            int Tg[16];
#pragma unroll
            for (int k = 0; k < 16; k++)
                Tg[k] = tag_at(tags, base + k * 32 + lane, is64);

            int len = 0;
#pragma unroll
            for (int k = 0; k < 16; k++)
                len += __popc(__ballot_sync(F, Tg[k] != -1));

            if (lane < 8) wait_flag(&flags[lane]);
            __syncwarp();

            float acc = 0.f;
            int carry = 0;
#pragma unroll
            for (int k = 0; k < 16; k++) {
                const int tt = k * 32 + lane;
                const int tg = Tg[k];
                const bool valid = tg >= 0;
                int tgp = __shfl_up_sync(F, tg, 1);
                if (lane == 0) tgp = carry;
                carry = __shfl_sync(F, Tg[k], 31);
                const int tgc = valid ? tg : 0;
                const int tgpc = tgp >= 0 ? tgp : 0;
                const float em = xrow[tt * 32 + tgc];
                const float tr = (tt == 0) ? __ldg(start_t + tgc)
                                           : __ldg(trans + tgpc * 32 + tgc);
                float c = valid ? (tr + em) : 0.f;
                if (valid && tt == len - 1) c += __ldg(end_t + tgc);
                acc += c;
            }
#pragma unroll
            for (int off = 16; off > 0; off >>= 1)
                acc += __shfl_xor_sync(F, acc, off);
            if (lane == 0) g_score[b] = acc;
        } else {
            // ---------- warp 0: DUAL alpha recursion (bA and bB interleaved) ----------
            const float* xA = g_x + (size_t)bA * SEQ * TAGS;
            const float* xB = g_x + (size_t)bB * SEQ * TAGS;
            int* flA = &g_flag[bA * 8];
            int* flB = &g_flag[bB * 8];

            int lenA = 0, lenB = 0;
#pragma unroll
            for (int k = 0; k < 16; k++) {
                const int ta = tag_at(tags, bA * SEQ + k * 32 + lane, is64);
                const int tb = tag_at(tags, bB * SEQ + k * 32 + lane, is64);
                lenA += __popc(__ballot_sync(F, ta != -1));
                lenB += __popc(__ballot_sync(F, tb != -1));
            }
            const int lmax = lenA > lenB ? lenA : lenB;

            float Tc[32];
#pragma unroll
            for (int i = 0; i < 32; i++)
                Tc[i] = __expf(__ldg(trans + i * 32 + lane));
            const float st = __ldg(start_t + lane);
            const float en = __ldg(end_t + lane);

            wait_flag(&flA[0]);
            wait_flag(&flB[0]);
            int last_ready = 0;

            float pA = __expf(st + xA[lane]);
            float pB = __expf(st + xB[lane]);
            float CA = 0.f, CB = 0.f;
            psA[0][lane] = pA;
            psB[0][lane] = pB;

            float EA[8], EB[8];
#pragma unroll
            for (int i = 0; i < 8; i++) {
                EA[i] = xA[(1 + i) * 32 + lane];
                EB[i] = xB[(1 + i) * 32 + lane];
            }

#define DUAL_STEP(i, bp, DO_RENORM, TT)                                        \
    {                                                                          \
        __syncwarp();                                                          \
        const bool vA = (TT) < lenA;                                           \
        const bool vB = (TT) < lenB;                                           \
        const float mA = psA[bp][0];                                           \
        const float mB = psB[bp][0];                                           \
        const float sA = dot32(&psA[bp][0], Tc);                               \
        const float sB = dot32(&psB[bp][0], Tc);                               \
        float pnA = sA * __expf(EA[i]);                                        \
        float pnB = sB * __expf(EB[i]);                                        \
        if (DO_RENORM) {                                                       \
            if (vA) {                                                          \
                float inv;                                                     \
                asm("rcp.approx.f32 %0, %1;" : "=f"(inv) : "f"(mA));           \
                pnA *= inv; CA += __logf(mA);                                  \
            }                                                                  \
            if (vB) {                                                          \
                float inv;                                                     \
                asm("rcp.approx.f32 %0, %1;" : "=f"(inv) : "f"(mB));           \
                pnB *= inv; CB += __logf(mB);                                  \
            }                                                                  \
        }                                                                      \
        pA = vA ? pnA : pA; psA[bp ^ 1][lane] = pA;                            \
        pB = vB ? pnB : pB; psB[bp ^ 1][lane] = pB;                            \
    }

#define PREFETCH(i, TN)                                                        \
    {                                                                          \
        const int tn = (TN);                                                   \
        const bool oA = tn < lenA, oB = tn < lenB;                             \
        EA[i] = oA ? xA[tn * 32 + lane] : 0.f;                                 \
        EB[i] = oB ? xB[tn * 32 + lane] : 0.f;                                 \
    }

            int t = 1;
            int bp = 0;
            while (t + 8 <= lmax) {
                int need = (t + 15) >> 6;
                if (need > 7) need = 7;
                while (last_ready < need) {
                    last_ready++;
                    wait_flag(&flA[last_ready]);
                    wait_flag(&flB[last_ready]);
                }
                DUAL_STEP(0, bp, false, t + 0); bp ^= 1; PREFETCH(0, t + 8);
                DUAL_STEP(1, bp, false, t + 1); bp ^= 1; PREFETCH(1, t + 9);
                DUAL_STEP(2, bp, false, t + 2); bp ^= 1; PREFETCH(2, t + 10);
                DUAL_STEP(3, bp, true,  t + 3); bp ^= 1; PREFETCH(3, t + 11);
                DUAL_STEP(4, bp, false, t + 4); bp ^= 1; PREFETCH(4, t + 12);
                DUAL_STEP(5, bp, false, t + 5); bp ^= 1; PREFETCH(5, t + 13);
                DUAL_STEP(6, bp, false, t + 6); bp ^= 1; PREFETCH(6, t + 14);
                DUAL_STEP(7, bp, true,  t + 7); bp ^= 1; PREFETCH(7, t + 15);
                t += 8;
            }
            // masked epilogue (<= 7 steps, no renorm; bounded growth safe)
#pragma unroll
            for (int i = 0; i < 7; i++) {
                DUAL_STEP(i, bp, false, t + i); bp ^= 1;
            }
#undef DUAL_STEP
#undef PREFETCH

            const float ee = __expf(en);
            float vA = pA * ee;
            float vB = pB * ee;
#pragma unroll
            for (int off = 16; off > 0; off >>= 1) {
                vA += __shfl_xor_sync(F, vA, off);
                vB += __shfl_xor_sync(F, vB, off);
            }
            if (lane == 0) {
                g_logz[bA] = CA + __logf(vA);
                g_logz[bB] = CB + __logf(vB);
            }
        }
    }

    __syncthreads();
    // reset this block's 16 flags for the next graph replay
    if (tid < 16) g_flag[bA * 8 + tid] = 0;

    // ticket: the last CRF block performs the final deterministic reduce
    if (tid == 0) {
        __threadfence();
        const int old = atomicAdd(&g_done, 1);
        s_last = (old == NCRF - 1);
    }
    __syncthreads();
    if (s_last && warp == 0) {
        __threadfence();
        float v = (g_score[lane] - g_logz[lane]) +
                  (g_score[lane + 32] - g_logz[lane + 32]);
#pragma unroll
        for (int off = 16; off > 0; off >>= 1)
            v += __shfl_xor_sync(F, v, off);
        if (lane == 0) {
            out[0] = -v * (1.0f / (float)BATCH);
            g_done = 0;
        }
    }
}

// ---------------------------------------------------------------------------
extern "C" void kernel_launch(void* const* d_in, const int* in_sizes, int n_in,
                              void* d_out, int out_size) {
    const float* feat    = (const float*)d_in[0];
    const int*   tags    = (const int*)  d_in[1];
    const float* W       = (const float*)d_in[2];
    const float* bias    = (const float*)d_in[3];
    const float* start_t = (const float*)d_in[4];
    const float* end_t   = (const float*)d_in[5];
    const float* trans   = (const float*)d_in[6];
    float* out = (float*)d_out;

    fused_kernel<<<NCRF + (BATCH * SEQ) / 64, 256>>>(
        feat, tags, W, bias, start_t, end_t, trans, out);
}

// round 8
// speedup vs baseline: 1.9582x; 1.9582x over previous
#include <cuda_runtime.h>
#include <cuda_bf16.h>
#include <cstdint>

#define BATCH 64
#define SEQ   512
#define DIM   1024
#define TAGS  32

// Per-(batch,chunk) chain outputs + combine state.
__device__ float g_fvec[BATCH][8][TAGS];
__device__ float g_bvec[BATCH][8][TAGS];
__device__ float g_flog[BATCH][8];
__device__ float g_blog[BATCH][8];
__device__ float g_scorep[BATCH][8];
__device__ float g_llh[BATCH];
__device__ int   g_len[BATCH];
__device__ int   g_doneb[BATCH];
__device__ int   g_done;

// ---------------------------------------------------------------------------
__device__ __forceinline__ void mma_bf16(float& d0, float& d1, float& d2, float& d3,
                                         uint32_t a0, uint32_t a1, uint32_t a2, uint32_t a3,
                                         uint32_t b0, uint32_t b1) {
    asm volatile(
        "mma.sync.aligned.m16n8k16.row.col.f32.bf16.bf16.f32 "
        "{%0,%1,%2,%3}, {%4,%5,%6,%7}, {%8,%9}, {%0,%1,%2,%3};\n"
        : "+f"(d0), "+f"(d1), "+f"(d2), "+f"(d3)
        : "r"(a0), "r"(a1), "r"(a2), "r"(a3), "r"(b0), "r"(b1));
}

__device__ __forceinline__ uint32_t pack_bf16(float lo, float hi) {
    __nv_bfloat162 h = __floats2bfloat162_rn(lo, hi);
    return *reinterpret_cast<uint32_t*>(&h);
}

__device__ __forceinline__ int tag_at(const int* __restrict__ tg, int idx, bool is64) {
    return is64 ? __ldg(tg + 2 * idx) : __ldg(tg + idx);
}

// 32-FMA dot of replicated vector (smem) with per-lane coefficients.
__device__ __forceinline__ float dot32(const float* __restrict__ q,
                                       const float* __restrict__ Tc) {
    const float4 q0 = *reinterpret_cast<const float4*>(q + 0);
    const float4 q1 = *reinterpret_cast<const float4*>(q + 4);
    const float4 q2 = *reinterpret_cast<const float4*>(q + 8);
    const float4 q3 = *reinterpret_cast<const float4*>(q + 12);
    const float4 q4 = *reinterpret_cast<const float4*>(q + 16);
    const float4 q5 = *reinterpret_cast<const float4*>(q + 20);
    const float4 q6 = *reinterpret_cast<const float4*>(q + 24);
    const float4 q7 = *reinterpret_cast<const float4*>(q + 28);
    float s0 = q0.x * Tc[0],  s1 = q0.y * Tc[1];
    float s2 = q0.z * Tc[2],  s3 = q0.w * Tc[3];
    s0 = fmaf(q1.x, Tc[4],  s0); s1 = fmaf(q1.y, Tc[5],  s1);
    s2 = fmaf(q1.z, Tc[6],  s2); s3 = fmaf(q1.w, Tc[7],  s3);
    s0 = fmaf(q2.x, Tc[8],  s0); s1 = fmaf(q2.y, Tc[9],  s1);
    s2 = fmaf(q2.z, Tc[10], s2); s3 = fmaf(q2.w, Tc[11], s3);
    s0 = fmaf(q3.x, Tc[12], s0); s1 = fmaf(q3.y, Tc[13], s1);
    s2 = fmaf(q3.z, Tc[14], s2); s3 = fmaf(q3.w, Tc[15], s3);
    s0 = fmaf(q4.x, Tc[16], s0); s1 = fmaf(q4.y, Tc[17], s1);
    s2 = fmaf(q4.z, Tc[18], s2); s3 = fmaf(q4.w, Tc[19], s3);
    s0 = fmaf(q5.x, Tc[20], s0); s1 = fmaf(q5.y, Tc[21], s1);
    s2 = fmaf(q5.z, Tc[22], s2); s3 = fmaf(q5.w, Tc[23], s3);
    s0 = fmaf(q6.x, Tc[24], s0); s1 = fmaf(q6.y, Tc[25], s1);
    s2 = fmaf(q6.z, Tc[26], s2); s3 = fmaf(q6.w, Tc[27], s3);
    s0 = fmaf(q7.x, Tc[28], s0); s1 = fmaf(q7.y, Tc[29], s1);
    s2 = fmaf(q7.z, Tc[30], s2); s3 = fmaf(q7.w, Tc[31], s3);
    return (s0 + s1) + (s2 + s3);
}

__device__ __forceinline__ float warp_len_count(const int* tags, int base, bool is64,
                                                int lane, int& len_out) {
    const unsigned F = 0xffffffffu;
    int len = 0;
#pragma unroll
    for (int k = 0; k < 16; k++) {
        const int tv = tag_at(tags, base + k * 32 + lane, is64);
        len += __popc(__ballot_sync(F, tv != -1));
    }
    len_out = len;
    return 0.f;
}

#define ASTRIDE 68
#define WSTRIDE 40

// ---------------------------------------------------------------------------
// One fused kernel: 512 blocks. Block = (batch b, chunk c). GEMM -> smem x,
// then warp0 fwd chain, warp1 bwd chain, warp2 numerator partial, tickets.
// ---------------------------------------------------------------------------
__global__ __launch_bounds__(256, 2)
void fused_kernel(const float* __restrict__ feat,
                  const int*   __restrict__ tags,
                  const float* __restrict__ Wg,
                  const float* __restrict__ bias,
                  const float* __restrict__ start_t,
                  const float* __restrict__ end_t,
                  const float* __restrict__ trans,
                  float* __restrict__ out) {
    __shared__ uint32_t Asm[64 * ASTRIDE];
    __shared__ uint32_t Wp [64 * WSTRIDE];
    __shared__ __align__(16) float xs[64 * 32];     // this chunk's emissions
    __shared__ __align__(16) float psF[2][32];
    __shared__ __align__(16) float psB[2][32];
    __shared__ int s_win, s_win2;

    const unsigned F = 0xffffffffu;
    const int tid  = threadIdx.x;
    const int lane = tid & 31;
    const int w    = tid >> 5;
    const int m0   = blockIdx.x * 64;
    const int b    = blockIdx.x >> 3;     // batch
    const int c    = blockIdx.x & 7;      // 64-step chunk

    // ======================= GEMM: x-chunk -> xs ==========================
    {
        float4 areg[8];
        float  wlo[8], whi[8];
#pragma unroll
        for (int i = 0; i < 8; i++) {
            const int idx = tid + i * 256;
            const int row = idx >> 5, kq = idx & 31;
            areg[i] = *reinterpret_cast<const float4*>(
                feat + (size_t)(m0 + row) * DIM + 4 * kq);
        }
#pragma unroll
        for (int i = 0; i < 8; i++) {
            const int idx = tid + i * 256;
            const int kp = idx >> 5, n = idx & 31;
            wlo[i] = Wg[(size_t)(2 * kp) * TAGS + n];
            whi[i] = Wg[(size_t)(2 * kp + 1) * TAGS + n];
        }

        float acc[2][4];
#pragma unroll
        for (int f = 0; f < 2; f++)
#pragma unroll
            for (int j = 0; j < 4; j++) acc[f][j] = 0.f;

        const int rb = (w & 3) * 16;
        const int nb = (w >> 2) * 16;
        const int g  = lane >> 2;
        const int t  = lane & 3;

        for (int cc = 0; cc < 8; cc++) {
#pragma unroll
            for (int i = 0; i < 8; i++) {
                const int idx = tid + i * 256;
                const int row = idx >> 5, kq = idx & 31;
                Asm[row * ASTRIDE + 2 * kq]     = pack_bf16(areg[i].x, areg[i].y);
                Asm[row * ASTRIDE + 2 * kq + 1] = pack_bf16(areg[i].z, areg[i].w);
            }
#pragma unroll
            for (int i = 0; i < 8; i++) {
                const int idx = tid + i * 256;
                const int kp = idx >> 5, n = idx & 31;
                Wp[kp * WSTRIDE + n] = pack_bf16(wlo[i], whi[i]);
            }
            __syncthreads();

            if (cc < 7) {
                const int kc = (cc + 1) * 128;
#pragma unroll
                for (int i = 0; i < 8; i++) {
                    const int idx = tid + i * 256;
                    const int row = idx >> 5, kq = idx & 31;
                    areg[i] = *reinterpret_cast<const float4*>(
                        feat + (size_t)(m0 + row) * DIM + kc + 4 * kq);
                }
#pragma unroll
                for (int i = 0; i < 8; i++) {
                    const int idx = tid + i * 256;
                    const int kp = idx >> 5, n = idx & 31;
                    wlo[i] = Wg[(size_t)(kc + 2 * kp) * TAGS + n];
                    whi[i] = Wg[(size_t)(kc + 2 * kp + 1) * TAGS + n];
                }
            }

#pragma unroll
            for (int kf = 0; kf < 8; kf++) {
                const int kw = 8 * kf;
                const uint32_t a0 = Asm[(rb + g)     * ASTRIDE + kw + t];
                const uint32_t a1 = Asm[(rb + g + 8) * ASTRIDE + kw + t];
                const uint32_t a2 = Asm[(rb + g)     * ASTRIDE + kw + 4 + t];
                const uint32_t a3 = Asm[(rb + g + 8) * ASTRIDE + kw + 4 + t];
#pragma unroll
                for (int f = 0; f < 2; f++) {
                    const uint32_t b0 = Wp[(kw + t)     * WSTRIDE + nb + 8 * f + g];
                    const uint32_t b1 = Wp[(kw + 4 + t) * WSTRIDE + nb + 8 * f + g];
                    mma_bf16(acc[f][0], acc[f][1], acc[f][2], acc[f][3],
                             a0, a1, a2, a3, b0, b1);
                }
            }
            __syncthreads();
        }

        // epilogue -> smem xs[lrow*32 + col]
        const int c2 = 2 * t;
        const int lrow = rb + g;
#pragma unroll
        for (int f = 0; f < 2; f++) {
            const int col = nb + 8 * f + c2;
            const float bv0 = bias[col], bv1 = bias[col + 1];
            *reinterpret_cast<float2*>(xs + lrow * 32 + col) =
                make_float2(acc[f][0] + bv0, acc[f][1] + bv1);
            *reinterpret_cast<float2*>(xs + (lrow + 8) * 32 + col) =
                make_float2(acc[f][2] + bv0, acc[f][3] + bv1);
        }
    }
    __syncthreads();   // xs ready for warps 0-2

    // ======================= chains + numerator ===========================
    // tag dtype detection
    const int v1 = tags[2 * lane + 1];
    const int v2 = tags[2 * lane + 65];
    const bool okd = (v1 == 0 || v1 == -1) && (v2 == 0 || v2 == -1);
    const bool is64 = __all_sync(F, okd);
    const int base = b * SEQ;

    if (w == 0) {
        // ----- forward chain: s_c ~ P_c * (c==0 ? p0 : 1), log in Cf -----
        int len; warp_len_count(tags, base, is64, lane, len);
        const int cl = (len - 1) >> 6;
        if (c <= cl - 1) {
            float Tc[32];
#pragma unroll
            for (int i = 0; i < 32; i++)
                Tc[i] = __expf(__ldg(trans + i * 32 + lane));

            float p, Cf = 0.f;
            int tloc, nst;
            if (c == 0) { p = __expf(__ldg(start_t + lane) + xs[lane]); tloc = 1;  nst = 63; }
            else        { p = 1.f;                                      tloc = 0;  nst = 64; }
            psF[0][lane] = p;
            int bp = 0;

#define FSTEP(RENORM)                                                          \
    {                                                                          \
        __syncwarp();                                                          \
        const float m_ = psF[bp][0];                                           \
        const float s_ = dot32(&psF[bp][0], Tc);                               \
        float pn = s_ * __expf(xs[tloc * 32 + lane]);                          \
        if (RENORM) {                                                          \
            float inv_;                                                        \
            asm("rcp.approx.f32 %0, %1;" : "=f"(inv_) : "f"(m_));              \
            pn *= inv_; Cf += __logf(m_);                                      \
        }                                                                      \
        p = pn; psF[bp ^ 1][lane] = p; bp ^= 1; tloc++;                        \
    }
            const int n4 = nst >> 2;
            for (int k = 0; k < n4; k++) { FSTEP(0) FSTEP(0) FSTEP(0) FSTEP(1) }
            const int rem = nst & 3;
            for (int k = 0; k < rem; k++) { FSTEP(0) }
#undef FSTEP
            // final renorm for range safety
            const float m = __shfl_sync(F, p, 0);
            float inv; asm("rcp.approx.f32 %0, %1;" : "=f"(inv) : "f"(m));
            p *= inv; Cf += __logf(m);
            g_fvec[b][c][lane] = p;
            if (lane == 0) g_flog[b][c] = Cf;
        }
    } else if (w == 1) {
        // ----- backward chain: g_c ~ P_c^T * (c==cl ? exp(end) : 1) -----
        int len; warp_len_count(tags, base, is64, lane, len);
        const int cl = (len - 1) >> 6;
        if (c >= 1 && c <= cl) {
            float Tr[32];
#pragma unroll
            for (int j = 0; j < 32; j++)
                Tr[j] = __expf(__ldg(trans + lane * 32 + j));

            const int lo = 64 * c;
            const int hi = (64 * c + 63 < len - 1) ? 64 * c + 63 : len - 1;
            const int nst = hi - lo + 1;
            float wv = (c == cl) ? __expf(__ldg(end_t + lane)) : 1.f;
            float Gb = 0.f;
            int tloc = hi - lo;      // local row of current step
            psB[0][lane] = wv * __expf(xs[tloc * 32 + lane]);
            int bp = 0;

#define BSTEP(RENORM)                                                          \
    {                                                                          \
        __syncwarp();                                                          \
        const float m_ = psB[bp][0];                                           \
        float s_ = dot32(&psB[bp][0], Tr);                                     \
        if (RENORM) {                                                          \
            float inv_;                                                        \
            asm("rcp.approx.f32 %0, %1;" : "=f"(inv_) : "f"(m_));              \
            s_ *= inv_; Gb += __logf(m_);                                      \
        }                                                                      \
        wv = s_;                                                               \
        tloc--;                                                                \
        const int il_ = tloc < 0 ? 0 : tloc;                                   \
        psB[bp ^ 1][lane] = wv * __expf(xs[il_ * 32 + lane]);                  \
        bp ^= 1;                                                               \
    }
            const int n4 = nst >> 2;
            for (int k = 0; k < n4; k++) { BSTEP(0) BSTEP(0) BSTEP(0) BSTEP(1) }
            const int rem = nst & 3;
            for (int k = 0; k < rem; k++) { BSTEP(0) }
#undef BSTEP
            const float m = __shfl_sync(F, wv, 0);
            float inv; asm("rcp.approx.f32 %0, %1;" : "=f"(inv) : "f"(m));
            wv *= inv; Gb += __logf(m);
            g_bvec[b][c][lane] = wv;
            if (lane == 0) g_blog[b][c] = Gb;
        }
    } else if (w == 2) {
        // ----- numerator partial score over rows [64c, 64c+63] -----
        int len; warp_len_count(tags, base, is64, lane, len);
        if (lane == 0) g_len[b] = len;
        float acc = 0.f;
#pragma unroll
        for (int r = 0; r < 2; r++) {
            const int t = 64 * c + r * 32 + lane;
            const int tg = tag_at(tags, base + t, is64);
            const bool valid = tg >= 0;
            int tgp = __shfl_up_sync(F, tg, 1);
            if (lane == 0) tgp = (t == 0) ? 0 : tag_at(tags, base + t - 1, is64);
            const int tgc = valid ? tg : 0;
            const int tgpc = tgp >= 0 ? tgp : 0;
            const float em = xs[(r * 32 + lane) * 32 + tgc];
            const float tr = (t == 0) ? __ldg(start_t + tgc)
                                      : __ldg(trans + tgpc * 32 + tgc);
            float co = valid ? (tr + em) : 0.f;
            if (valid && t == len - 1) co += __ldg(end_t + tgc);
            acc += co;
        }
#pragma unroll
        for (int off = 16; off > 0; off >>= 1)
            acc += __shfl_xor_sync(F, acc, off);
        if (lane == 0) g_scorep[b][c] = acc;
    }

    // ======================= tickets + combine ============================
    __syncthreads();
    if (tid == 0) {
        __threadfence();
        const int old = atomicAdd(&g_doneb[b], 1);
        s_win = (old == 7);
        s_win2 = 0;
    }
    __syncthreads();
    if (!s_win) return;

    if (w == 0) {
        // per-batch combine (warp 0)
        __threadfence();
        const int len = g_len[b];
        const int cl = (len - 1) >> 6;
        float sprev = g_fvec[b][0][lane];
        float L = g_flog[b][0];
        for (int cc = 1; cc < cl; cc++) {
            float d = g_bvec[b][cc][lane] * sprev;
            float sc = g_fvec[b][cc][lane];
            float s2 = sc;
#pragma unroll
            for (int off = 16; off > 0; off >>= 1) {
                d  += __shfl_xor_sync(F, d, off);
                s2 += __shfl_xor_sync(F, s2, off);
            }
            L += g_blog[b][cc] + __logf(d) - __logf(s2);
            sprev = sc;
        }
        float d = g_bvec[b][cl][lane] * sprev;
#pragma unroll
        for (int off = 16; off > 0; off >>= 1)
            d += __shfl_xor_sync(F, d, off);
        const float logZ = L + g_blog[b][cl] + __logf(d);

        float score = 0.f;
        if (lane == 0) {
#pragma unroll
            for (int cc = 0; cc < 8; cc++) score += g_scorep[b][cc];
            g_llh[b] = score - logZ;
        }
    }
    __syncthreads();
    if (tid == 0) {
        __threadfence();
        const int o2 = atomicAdd(&g_done, 1);
        s_win2 = (o2 == BATCH - 1);
    }
    __syncthreads();
    if (s_win2 && w == 0) {
        __threadfence();
        float v = g_llh[lane] + g_llh[lane + 32];
#pragma unroll
        for (int off = 16; off > 0; off >>= 1)
            v += __shfl_xor_sync(F, v, off);
        if (lane == 0) out[0] = -v * (1.0f / (float)BATCH);
        // reset tickets for the next graph replay
        g_doneb[lane] = 0;
        g_doneb[lane + 32] = 0;
        if (lane == 0) g_done = 0;
    }
}

// ---------------------------------------------------------------------------
extern "C" void kernel_launch(void* const* d_in, const int* in_sizes, int n_in,
                              void* d_out, int out_size) {
    const float* feat    = (const float*)d_in[0];
    const int*   tags    = (const int*)  d_in[1];
    const float* W       = (const float*)d_in[2];
    const float* bias    = (const float*)d_in[3];
    const float* start_t = (const float*)d_in[4];
    const float* end_t   = (const float*)d_in[5];
    const float* trans   = (const float*)d_in[6];
    float* out = (float*)d_out;

    fused_kernel<<<BATCH * 8, 256>>>(feat, tags, W, bias,
                                     start_t, end_t, trans, out);
}